// round 3
// baseline (speedup 1.0000x reference)
#include <cuda_runtime.h>

#define BATCH 8
#define DIM   512
#define ODIM  1536      // 3 * DIM
#define HH    64
#define WW    64
#define NPIX  4096      // HH*WW
#define ND    4         // dilations 1,2,4,8

// ---------------- scratch (allocation-free: __device__ globals) ----------------
__device__ float g_qkv[(size_t)BATCH * ODIM * NPIX];   // 201 MB
__device__ float g_pooled[BATCH * DIM];
__device__ float g_gate[BATCH * ND];

// ---------------- global average pool: pooled[b,c] = mean(x[b,c,:,:]) ----------
__global__ void pool_kernel(const float* __restrict__ x) {
    int bc = blockIdx.x;                       // b*DIM + c, 4096 blocks
    const float4* p = (const float4*)(x + (size_t)bc * NPIX);
    float sum = 0.f;
#pragma unroll
    for (int it = 0; it < 8; it++) {           // 1024 float4 / 128 threads
        float4 v = p[threadIdx.x + it * 128];
        sum += v.x + v.y + v.z + v.w;
    }
    __shared__ float red[4];
#pragma unroll
    for (int o = 16; o > 0; o >>= 1) sum += __shfl_down_sync(0xffffffffu, sum, o);
    if ((threadIdx.x & 31) == 0) red[threadIdx.x >> 5] = sum;
    __syncthreads();
    if (threadIdx.x == 0)
        g_pooled[bc] = (red[0] + red[1] + red[2] + red[3]) * (1.f / NPIX);
}

// ---------------- gate: softmax(pooled @ w_gate^T + b_gate) --------------------
__global__ void gate_kernel(const float* __restrict__ wg, const float* __restrict__ bg) {
    int b = blockIdx.x;                 // 8 blocks, 128 threads = 4 warps
    int w = threadIdx.x >> 5;           // warp -> dilation index
    int lane = threadIdx.x & 31;
    float sum = 0.f;
    for (int c = lane; c < DIM; c += 32)
        sum += g_pooled[b * DIM + c] * wg[w * DIM + c];
#pragma unroll
    for (int o = 16; o > 0; o >>= 1) sum += __shfl_down_sync(0xffffffffu, sum, o);
    __shared__ float logits[ND];
    if (lane == 0) logits[w] = sum + bg[w];
    __syncthreads();
    if (threadIdx.x == 0) {
        float mx = logits[0];
#pragma unroll
        for (int i = 1; i < ND; i++) mx = fmaxf(mx, logits[i]);
        float den = 0.f, e[ND];
#pragma unroll
        for (int i = 0; i < ND; i++) { e[i] = expf(logits[i] - mx); den += e[i]; }
        float inv = 1.f / den;
#pragma unroll
        for (int i = 0; i < ND; i++) g_gate[b * ND + i] = e[i] * inv;
    }
}

// ---------------- qkv GEMM: C[b] = w_qkv(1536x512) @ x[b](512x4096) ------------
// 128x128 tile, BK=8, 256 threads, 8x8 micro-tile, float4 global loads,
// double-buffered shared memory (prefetch next K-slice during compute).
__global__ __launch_bounds__(256) void gemm_kernel(const float* __restrict__ W,
                                                   const float* __restrict__ X) {
    const int b = blockIdx.z;
    const float* Bp = X + (size_t)b * DIM * NPIX;
    float* Cp = g_qkv + (size_t)b * ODIM * NPIX;
    const int bm = blockIdx.y * 128;
    const int bn = blockIdx.x * 128;

    __shared__ float As[2][8][128];
    __shared__ float Bs[2][8][128];

    const int tid  = threadIdx.x;
    const int arow = tid >> 1;            // 0..127
    const int acol = (tid & 1) * 4;       // 0 or 4
    const int brow = tid >> 5;            // 0..7
    const int bcol = (tid & 31) * 4;      // 0..124
    const int tr   = (tid >> 4) * 8;      // 0..120 (M offset)
    const int tc   = (tid & 15) * 8;      // 0..120 (N offset)

    const float* aptr = W  + (size_t)(bm + arow) * DIM + acol;
    const float* bptr = Bp + (size_t)brow * NPIX + bn + bcol;

    float acc[8][8] = {};
    float af[8], bf[8];

    // preload k0 = 0 into buffer 0
    float4 av = *(const float4*)(aptr);
    float4 bv = *(const float4*)(bptr);
    As[0][acol + 0][arow] = av.x;
    As[0][acol + 1][arow] = av.y;
    As[0][acol + 2][arow] = av.z;
    As[0][acol + 3][arow] = av.w;
    *(float4*)&Bs[0][brow][bcol] = bv;
    __syncthreads();

    int buf = 0;
    for (int k0 = 0; k0 < DIM; k0 += 8) {
        // prefetch next K-slice into registers (no smem touch yet)
        if (k0 + 8 < DIM) {
            av = *(const float4*)(aptr + k0 + 8);
            bv = *(const float4*)(bptr + (size_t)(k0 + 8) * NPIX);
        }
#pragma unroll
        for (int kk = 0; kk < 8; kk++) {
            *(float4*)&af[0] = *(float4*)&As[buf][kk][tr];
            *(float4*)&af[4] = *(float4*)&As[buf][kk][tr + 4];
            *(float4*)&bf[0] = *(float4*)&Bs[buf][kk][tc];
            *(float4*)&bf[4] = *(float4*)&Bs[buf][kk][tc + 4];
#pragma unroll
            for (int m = 0; m < 8; m++)
#pragma unroll
                for (int n = 0; n < 8; n++)
                    acc[m][n] = fmaf(af[m], bf[n], acc[m][n]);
        }
        if (k0 + 8 < DIM) {
            int nxt = buf ^ 1;
            As[nxt][acol + 0][arow] = av.x;
            As[nxt][acol + 1][arow] = av.y;
            As[nxt][acol + 2][arow] = av.z;
            As[nxt][acol + 3][arow] = av.w;
            *(float4*)&Bs[nxt][brow][bcol] = bv;
            __syncthreads();
            buf = nxt;
        }
    }
#pragma unroll
    for (int m = 0; m < 8; m++) {
        float* dst = Cp + (size_t)(bm + tr + m) * NPIX + bn + tc;
        *(float4*)(dst)     = make_float4(acc[m][0], acc[m][1], acc[m][2], acc[m][3]);
        *(float4*)(dst + 4) = make_float4(acc[m][4], acc[m][5], acc[m][6], acc[m][7]);
    }
}

// ---------------- dilated 3x3 attention + gate + write -------------------------
// One thread per (b, dilation, head, pixel). hd = 64, scale = 0.125.
// OOB taps: score = 0 (counted in softmax denominator), v contribution = 0.
// Mask applied ONCE after accumulation (m in {0,1}: m*sum(qk) == sum(q*k*m)).
__global__ __launch_bounds__(128) void attn_kernel(float* __restrict__ out) {
    const int n  = blockIdx.x * 128 + threadIdx.x;   // pixel 0..4095
    const int ih = blockIdx.y;                       // i*2 + h, 0..7
    const int b  = blockIdx.z;
    const int i  = ih >> 1;
    const int h  = ih & 1;
    const int dil = 1 << i;                          // 1,2,4,8
    const int y = n >> 6;
    const int x = n & 63;

    const size_t plane = NPIX;
    const size_t chan0 = (size_t)b * ODIM + i * 128 + h * 64;
    const float* qb = g_qkv + (chan0)         * plane;   // s = 0
    const float* kb = g_qkv + (chan0 + DIM)   * plane;   // s = 1
    const float* vb = g_qkv + (chan0 + 2*DIM) * plane;   // s = 2

    int   off[9];
    float valm[9];
#pragma unroll
    for (int t = 0; t < 9; t++) {
        int yy = y + (t / 3 - 1) * dil;
        int xx = x + (t % 3 - 1) * dil;
        bool ok = (yy >= 0) & (yy < HH) & (xx >= 0) & (xx < WW);
        valm[t] = ok ? 1.f : 0.f;
        off[t]  = ok ? (yy * WW + xx) : 0;
    }

    float s[9] = {0.f, 0.f, 0.f, 0.f, 0.f, 0.f, 0.f, 0.f, 0.f};
#pragma unroll 4
    for (int dd = 0; dd < 64; dd++) {
        float qv = qb[(size_t)dd * plane + n];
        const float* kd = kb + (size_t)dd * plane;
#pragma unroll
        for (int t = 0; t < 9; t++)
            s[t] = fmaf(qv, kd[off[t]], s[t]);
    }

    // softmax over 9 taps (invalid taps have score exactly 0, like the reference)
    float mx = -1e30f;
#pragma unroll
    for (int t = 0; t < 9; t++) { s[t] *= 0.125f * valm[t]; mx = fmaxf(mx, s[t]); }
    float p[9], den = 0.f;
#pragma unroll
    for (int t = 0; t < 9; t++) { p[t] = expf(s[t] - mx); den += p[t]; }
    const float gatev = g_gate[b * ND + i];
    const float inv = gatev / den;
#pragma unroll
    for (int t = 0; t < 9; t++) p[t] = p[t] * inv * valm[t];  // kill OOB v taps

    float* ob = out + ((size_t)b * DIM + i * 128 + h * 64) * plane + n;
#pragma unroll 4
    for (int dd = 0; dd < 64; dd++) {
        const float* vd = vb + (size_t)dd * plane;
        float acc = 0.f;
#pragma unroll
        for (int t = 0; t < 9; t++)
            acc = fmaf(p[t], vd[off[t]], acc);
        ob[(size_t)dd * plane] = acc;
    }
}

// ---------------- launch ----------------
extern "C" void kernel_launch(void* const* d_in, const int* in_sizes, int n_in,
                              void* d_out, int out_size) {
    const float* x      = (const float*)d_in[0];   // [8,512,64,64]
    const float* w_qkv  = (const float*)d_in[1];   // [1536,512]
    const float* w_gate = (const float*)d_in[2];   // [4,512]
    const float* b_gate = (const float*)d_in[3];   // [4]
    float* out = (float*)d_out;                    // [8,512,64,64]

    pool_kernel<<<BATCH * DIM, 128>>>(x);
    gate_kernel<<<BATCH, 128>>>(w_gate, b_gate);

    dim3 ggrid(NPIX / 128, ODIM / 128, BATCH);     // 32 x 12 x 8
    gemm_kernel<<<ggrid, 256>>>(w_qkv, x);

    dim3 agrid(NPIX / 128, 8, BATCH);              // pixels x (dil*head) x batch
    attn_kernel<<<agrid, 128>>>(out);
}

// round 4
// speedup vs baseline: 1.2241x; 1.2241x over previous
#include <cuda_runtime.h>
#include <cstdint>

#define BATCH 8
#define DIM   512
#define ODIM  1536      // 3 * DIM
#define HH    64
#define WW    64
#define NPIX  4096      // HH*WW
#define ND    4         // dilations 1,2,4,8

// ---------------- scratch (allocation-free: __device__ globals) ----------------
__device__ float g_qkv[(size_t)BATCH * ODIM * NPIX];   // 201 MB
__device__ float g_pooled[BATCH * DIM];
__device__ float g_gate[BATCH * ND];

// ---------------- global average pool ----------------
__global__ void pool_kernel(const float* __restrict__ x) {
    int bc = blockIdx.x;
    const float4* p = (const float4*)(x + (size_t)bc * NPIX);
    float sum = 0.f;
#pragma unroll
    for (int it = 0; it < 8; it++) {
        float4 v = p[threadIdx.x + it * 128];
        sum += v.x + v.y + v.z + v.w;
    }
    __shared__ float red[4];
#pragma unroll
    for (int o = 16; o > 0; o >>= 1) sum += __shfl_down_sync(0xffffffffu, sum, o);
    if ((threadIdx.x & 31) == 0) red[threadIdx.x >> 5] = sum;
    __syncthreads();
    if (threadIdx.x == 0)
        g_pooled[bc] = (red[0] + red[1] + red[2] + red[3]) * (1.f / NPIX);
}

// ---------------- gate softmax ----------------
__global__ void gate_kernel(const float* __restrict__ wg, const float* __restrict__ bg) {
    int b = blockIdx.x;
    int w = threadIdx.x >> 5;
    int lane = threadIdx.x & 31;
    float sum = 0.f;
    for (int c = lane; c < DIM; c += 32)
        sum += g_pooled[b * DIM + c] * wg[w * DIM + c];
#pragma unroll
    for (int o = 16; o > 0; o >>= 1) sum += __shfl_down_sync(0xffffffffu, sum, o);
    __shared__ float logits[ND];
    if (lane == 0) logits[w] = sum + bg[w];
    __syncthreads();
    if (threadIdx.x == 0) {
        float mx = logits[0];
#pragma unroll
        for (int i = 1; i < ND; i++) mx = fmaxf(mx, logits[i]);
        float den = 0.f, e[ND];
#pragma unroll
        for (int i = 0; i < ND; i++) { e[i] = expf(logits[i] - mx); den += e[i]; }
        float inv = 1.f / den;
#pragma unroll
        for (int i = 0; i < ND; i++) g_gate[b * ND + i] = e[i] * inv;
    }
}

// ---------------- tf32x3 tensor-core GEMM -------------------------------------
// C[b](1536x4096) = W(1536x512) @ X[b](512x4096), fp32-accurate via hi/lo split.
// 128x128 block tile, 8 warps (2M x 4N), warp tile 64x32, mma.m16n8k8.tf32.
__device__ __forceinline__ uint32_t f2tf32(float x) {
    uint32_t r;
    asm("cvt.rna.tf32.f32 %0, %1;" : "=r"(r) : "f"(x));
    return r;
}
__device__ __forceinline__ void mma_tf32(float c[4],
                                         uint32_t a0, uint32_t a1, uint32_t a2, uint32_t a3,
                                         uint32_t b0, uint32_t b1) {
    asm volatile("mma.sync.aligned.m16n8k8.row.col.f32.tf32.tf32.f32 "
                 "{%0,%1,%2,%3}, {%4,%5,%6,%7}, {%8,%9}, {%0,%1,%2,%3};"
                 : "+f"(c[0]), "+f"(c[1]), "+f"(c[2]), "+f"(c[3])
                 : "r"(a0), "r"(a1), "r"(a2), "r"(a3), "r"(b0), "r"(b1));
}

#define SPAD 136   // 128 + 8: row-stride mod 32 == 8 -> conflict-free fragment LDS

__global__ __launch_bounds__(256) void gemm_kernel(const float* __restrict__ W,
                                                   const float* __restrict__ X) {
    const int b = blockIdx.z;
    const float* Bp = X + (size_t)b * DIM * NPIX;
    float* Cp = g_qkv + (size_t)b * ODIM * NPIX;
    const int bm = blockIdx.y * 128;
    const int bn = blockIdx.x * 128;

    __shared__ __align__(16) float As[2][16][SPAD];   // [k][m]
    __shared__ __align__(16) float Bs[2][16][SPAD];   // [k][n]

    const int tid  = threadIdx.x;
    const int lane = tid & 31;
    const int wid  = tid >> 5;
    const int g    = lane >> 2;       // groupID 0..7
    const int tig  = lane & 3;        // threadID_in_group
    const int wm   = (wid >> 2) * 64; // warp M offset
    const int wn   = (wid & 3) * 32;  // warp N offset

    // gmem -> smem mapping (2 float4 per thread per operand)
    const int ar = tid >> 2;          // A m-row 0..63 (+64)
    const int ac = (tid & 3) * 4;     // A k-col
    const int br = tid >> 5;          // B k-row 0..7 (+8)
    const int bc = (tid & 31) * 4;    // B n-col

    const float* aP0 = W  + (size_t)(bm + ar) * DIM + ac;
    const float* aP1 = aP0 + (size_t)64 * DIM;
    const float* bP0 = Bp + (size_t)br * NPIX + bn + bc;
    const float* bP1 = bP0 + (size_t)8 * NPIX;

    float acc[4][4][4] = {};          // [mt][nt][c0..c3]

    // preload k-tile 0 into buffer 0
    float4 a0v = *(const float4*)(aP0);
    float4 a1v = *(const float4*)(aP1);
    float4 b0v = *(const float4*)(bP0);
    float4 b1v = *(const float4*)(bP1);
    As[0][ac + 0][ar] = a0v.x;  As[0][ac + 1][ar] = a0v.y;
    As[0][ac + 2][ar] = a0v.z;  As[0][ac + 3][ar] = a0v.w;
    As[0][ac + 0][ar + 64] = a1v.x;  As[0][ac + 1][ar + 64] = a1v.y;
    As[0][ac + 2][ar + 64] = a1v.z;  As[0][ac + 3][ar + 64] = a1v.w;
    *(float4*)&Bs[0][br][bc]     = b0v;
    *(float4*)&Bs[0][br + 8][bc] = b1v;
    __syncthreads();

    int buf = 0;
    const int NKT = DIM / 16;   // 32 k-tiles
    for (int kt = 0; kt < NKT; kt++) {
        if (kt + 1 < NKT) {
            a0v = *(const float4*)(aP0 + 16 * (kt + 1));
            a1v = *(const float4*)(aP1 + 16 * (kt + 1));
            b0v = *(const float4*)(bP0 + (size_t)16 * (kt + 1) * NPIX);
            b1v = *(const float4*)(bP1 + (size_t)16 * (kt + 1) * NPIX);
        }
#pragma unroll
        for (int ks = 0; ks < 2; ks++) {
            const int kb = ks * 8;
            uint32_t ahi[4][4], alo[4][4];
#pragma unroll
            for (int mt = 0; mt < 4; mt++) {
                const int m0 = wm + mt * 16 + g;
                float x0 = As[buf][kb + tig    ][m0];
                float x1 = As[buf][kb + tig    ][m0 + 8];
                float x2 = As[buf][kb + tig + 4][m0];
                float x3 = As[buf][kb + tig + 4][m0 + 8];
                ahi[mt][0] = f2tf32(x0); alo[mt][0] = f2tf32(x0 - __uint_as_float(ahi[mt][0]));
                ahi[mt][1] = f2tf32(x1); alo[mt][1] = f2tf32(x1 - __uint_as_float(ahi[mt][1]));
                ahi[mt][2] = f2tf32(x2); alo[mt][2] = f2tf32(x2 - __uint_as_float(ahi[mt][2]));
                ahi[mt][3] = f2tf32(x3); alo[mt][3] = f2tf32(x3 - __uint_as_float(ahi[mt][3]));
            }
#pragma unroll
            for (int nt = 0; nt < 4; nt++) {
                const int n0 = wn + nt * 8 + g;
                float y0 = Bs[buf][kb + tig    ][n0];
                float y1 = Bs[buf][kb + tig + 4][n0];
                uint32_t bh0 = f2tf32(y0), bl0 = f2tf32(y0 - __uint_as_float(bh0));
                uint32_t bh1 = f2tf32(y1), bl1 = f2tf32(y1 - __uint_as_float(bh1));
#pragma unroll
                for (int mt = 0; mt < 4; mt++) {
                    // small terms first, then hi*hi
                    mma_tf32(acc[mt][nt], alo[mt][0], alo[mt][1], alo[mt][2], alo[mt][3], bh0, bh1);
                    mma_tf32(acc[mt][nt], ahi[mt][0], ahi[mt][1], ahi[mt][2], ahi[mt][3], bl0, bl1);
                    mma_tf32(acc[mt][nt], ahi[mt][0], ahi[mt][1], ahi[mt][2], ahi[mt][3], bh0, bh1);
                }
            }
        }
        if (kt + 1 < NKT) {
            const int nxt = buf ^ 1;
            As[nxt][ac + 0][ar] = a0v.x;  As[nxt][ac + 1][ar] = a0v.y;
            As[nxt][ac + 2][ar] = a0v.z;  As[nxt][ac + 3][ar] = a0v.w;
            As[nxt][ac + 0][ar + 64] = a1v.x;  As[nxt][ac + 1][ar + 64] = a1v.y;
            As[nxt][ac + 2][ar + 64] = a1v.z;  As[nxt][ac + 3][ar + 64] = a1v.w;
            *(float4*)&Bs[nxt][br][bc]     = b0v;
            *(float4*)&Bs[nxt][br + 8][bc] = b1v;
            __syncthreads();
            buf = nxt;
        }
    }

    // epilogue: c0,c1 at (row g, cols 2*tig, 2*tig+1); c2,c3 at row g+8
#pragma unroll
    for (int mt = 0; mt < 4; mt++) {
        const int r0 = bm + wm + mt * 16 + g;
#pragma unroll
        for (int nt = 0; nt < 4; nt++) {
            const int c0 = bn + wn + nt * 8 + tig * 2;
            *(float2*)(Cp + (size_t)r0 * NPIX + c0)       = make_float2(acc[mt][nt][0], acc[mt][nt][1]);
            *(float2*)(Cp + (size_t)(r0 + 8) * NPIX + c0) = make_float2(acc[mt][nt][2], acc[mt][nt][3]);
        }
    }
}

// ---------------- dilated 3x3 attention + gate + write -------------------------
__global__ __launch_bounds__(128) void attn_kernel(float* __restrict__ out) {
    const int n  = blockIdx.x * 128 + threadIdx.x;
    const int ih = blockIdx.y;
    const int b  = blockIdx.z;
    const int i  = ih >> 1;
    const int h  = ih & 1;
    const int dil = 1 << i;
    const int y = n >> 6;
    const int x = n & 63;

    const size_t plane = NPIX;
    const size_t chan0 = (size_t)b * ODIM + i * 128 + h * 64;
    const float* qb = g_qkv + (chan0)         * plane;
    const float* kb = g_qkv + (chan0 + DIM)   * plane;
    const float* vb = g_qkv + (chan0 + 2*DIM) * plane;

    int   off[9];
    float valm[9];
#pragma unroll
    for (int t = 0; t < 9; t++) {
        int yy = y + (t / 3 - 1) * dil;
        int xx = x + (t % 3 - 1) * dil;
        bool ok = (yy >= 0) & (yy < HH) & (xx >= 0) & (xx < WW);
        valm[t] = ok ? 1.f : 0.f;
        off[t]  = ok ? (yy * WW + xx) : 0;
    }

    float s[9] = {0.f, 0.f, 0.f, 0.f, 0.f, 0.f, 0.f, 0.f, 0.f};
#pragma unroll 4
    for (int dd = 0; dd < 64; dd++) {
        float qv = qb[(size_t)dd * plane + n];
        const float* kd = kb + (size_t)dd * plane;
#pragma unroll
        for (int t = 0; t < 9; t++)
            s[t] = fmaf(qv, kd[off[t]], s[t]);
    }

    float mx = -1e30f;
#pragma unroll
    for (int t = 0; t < 9; t++) { s[t] *= 0.125f * valm[t]; mx = fmaxf(mx, s[t]); }
    float p[9], den = 0.f;
#pragma unroll
    for (int t = 0; t < 9; t++) { p[t] = expf(s[t] - mx); den += p[t]; }
    const float gatev = g_gate[b * ND + i];
    const float inv = gatev / den;
#pragma unroll
    for (int t = 0; t < 9; t++) p[t] = p[t] * inv * valm[t];

    float* ob = out + ((size_t)b * DIM + i * 128 + h * 64) * plane + n;
#pragma unroll 4
    for (int dd = 0; dd < 64; dd++) {
        const float* vd = vb + (size_t)dd * plane;
        float acc = 0.f;
#pragma unroll
        for (int t = 0; t < 9; t++)
            acc = fmaf(p[t], vd[off[t]], acc);
        ob[(size_t)dd * plane] = acc;
    }
}

// ---------------- launch ----------------
extern "C" void kernel_launch(void* const* d_in, const int* in_sizes, int n_in,
                              void* d_out, int out_size) {
    const float* x      = (const float*)d_in[0];
    const float* w_qkv  = (const float*)d_in[1];
    const float* w_gate = (const float*)d_in[2];
    const float* b_gate = (const float*)d_in[3];
    float* out = (float*)d_out;

    pool_kernel<<<BATCH * DIM, 128>>>(x);
    gate_kernel<<<BATCH, 128>>>(w_gate, b_gate);

    dim3 ggrid(NPIX / 128, ODIM / 128, BATCH);     // 32 x 12 x 8
    gemm_kernel<<<ggrid, 256>>>(w_qkv, x);

    dim3 agrid(NPIX / 128, 8, BATCH);
    attn_kernel<<<agrid, 128>>>(out);
}